// round 14
// baseline (speedup 1.0000x reference)
#include <cuda_runtime.h>
#include <cstdio>

#define BASE 2048
#define CDIM 512
#define QDIM 256
#define TOT  2816
#define CE   2560
#define NN   ((size_t)TOT * (size_t)TOT)

__device__ __forceinline__ float sget(const float* p, float fb) { return p ? *p : fb; }

// diagonal entry of H at (i,i), computed inline (FP64, run by few threads)
__device__ __forceinline__ float diag_val(int i, const float* srp, const float* sip) {
    double sr = (double)sget(srp, 2.0f);
    double si = (double)sget(sip, 14.134725f);
    if (i < BASE) {
        double ln = log((double)(i + 1));
        double lr = -sr * ln, li = -si * ln;
        bool small_s = (fabs(sr) < 20.0) && (fabs(si) < 200.0);
        double zre = (small_s || lr > -50.0) ? exp(lr) * cos(li) : 1e-50;
        return (float)(zre + 1e-20);
    } else if (i < CE) {
        return 1e-20f;
    } else {
        double smag = sqrt(sr * sr + si * si);
        double ent = (-smag * log(smag + 1e-10)) * (1.0 + 0.1 * sin(si / 10.0));
        return (float)(ent / (double)(i - CE + 1) + 1e-20);
    }
}

__device__ __forceinline__ float gamma_re(int i, int j,
                                          const float* __restrict__ gs,
                                          const float* __restrict__ gr) {
    float br = 0.f, cr = 0.f;
    #pragma unroll
    for (int g = 0; g < 4; g++) {
        float s2 = (float)(g + 5) * 1e-26f;   // (g+5)*theta_c/10
        br += s2 * gr[g * 256 + i * 16 + j];
        cr += s2 * gr[g * 256 + j * 16 + i];
        if (i < 8 && j < 8) {
            float s1 = (float)(g + 1) * 1e-26f;
            br += s1 * gs[g * 64 + i * 8 + j];
            cr += s1 * gs[g * 64 + j * 8 + i];
        }
    }
    return 0.5f * (br + cr);
}

// ============ single fast kernel: real in / real out, 64x64 float4 tiles ====
__global__ __launch_bounds__(256)
void fill_fast(const float* __restrict__ cc, const float* __restrict__ crm,
               const float* __restrict__ v,
               const float* __restrict__ gs, const float* __restrict__ gr,
               const float* __restrict__ srp, const float* __restrict__ sip,
               float* __restrict__ out) {
    __shared__ float sm[64][65];
    const int bx = blockIdx.x, by = blockIdx.y;
    const int t  = threadIdx.x;
    const int rb = t >> 4;               // 0..15
    const int c4 = (t & 15) << 2;        // 0,4,...,60
    const int i0 = by * 64, j0 = bx * 64;
    const bool isdiag = (bx == by);

    if (by < 32) {
        if (bx < 32) {
            // ---- base x base: sc*(cc[i,j] + cc[j,i]) (+diag, +gamma corner)
            #pragma unroll
            for (int p = 0; p < 4; p++) {
                int r = rb + 16 * p;
                float4 m = *(const float4*)(cc + (size_t)(j0 + r) * BASE + i0 + c4);
                sm[r][c4] = m.x; sm[r][c4 + 1] = m.y; sm[r][c4 + 2] = m.z; sm[r][c4 + 3] = m.w;
            }
            __syncthreads();
            const float sc = 0.5e-27f;
            const bool corner = (i0 == 0 && j0 == 0);
            #pragma unroll
            for (int p = 0; p < 4; p++) {
                int r = rb + 16 * p, i = i0 + r;
                float4 a = *(const float4*)(cc + (size_t)i * BASE + j0 + c4);
                float4 o;
                o.x = sc * (a.x + sm[c4 + 0][r]);
                o.y = sc * (a.y + sm[c4 + 1][r]);
                o.z = sc * (a.z + sm[c4 + 2][r]);
                o.w = sc * (a.w + sm[c4 + 3][r]);
                if (corner && r < 16 && c4 < 16) {
                    #pragma unroll
                    for (int k = 0; k < 4; k++)
                        (&o.x)[k] += gamma_re(r, c4 + k, gs, gr);
                }
                if (isdiag) {
                    int dj = i - (j0 + c4);
                    if ((unsigned)dj < 4u) (&o.x)[dj] += diag_val(i, srp, sip);
                }
                *(float4*)(out + (size_t)i * TOT + j0 + c4) = o;
            }
        } else if (bx < 40) {
            // ---- right strip: out[i, BASE+jc] = crm[jc, i] (transpose)
            const int jc0 = (bx - 32) * 64;
            #pragma unroll
            for (int p = 0; p < 4; p++) {
                int r = rb + 16 * p;
                float4 m = *(const float4*)(crm + (size_t)(jc0 + r) * BASE + i0 + c4);
                sm[r][c4] = m.x; sm[r][c4 + 1] = m.y; sm[r][c4 + 2] = m.z; sm[r][c4 + 3] = m.w;
            }
            __syncthreads();
            #pragma unroll
            for (int p = 0; p < 4; p++) {
                int r = rb + 16 * p, i = i0 + r;
                float4 o = make_float4(sm[c4 + 0][r], sm[c4 + 1][r],
                                       sm[c4 + 2][r], sm[c4 + 3][r]);
                *(float4*)(out + (size_t)i * TOT + j0 + c4) = o;
            }
        } else {
            // ---- top-right zeros
            const float4 z = make_float4(0.f, 0.f, 0.f, 0.f);
            #pragma unroll
            for (int p = 0; p < 4; p++) {
                int i = i0 + rb + 16 * p;
                *(float4*)(out + (size_t)i * TOT + j0 + c4) = z;
            }
        }
    } else if (by < 40) {
        if (bx < 32) {
            // ---- bottom-left: Re(conj(crm[ic, j])) = crm[ic, j]  (direct copy)
            const int ic0 = (by - 32) * 64;
            #pragma unroll
            for (int p = 0; p < 4; p++) {
                int r = rb + 16 * p;
                float4 a = *(const float4*)(crm + (size_t)(ic0 + r) * BASE + j0 + c4);
                *(float4*)(out + (size_t)(i0 + r) * TOT + j0 + c4) = a;
            }
        } else if (bx < 40) {
            // ---- consciousness outer product: s * v_i * v_j  (+1e-20 diag)
            __shared__ float rd[256];
            {
                float a = v[t], b = v[t + 256];
                rd[t] = a * a + b * b;
            }
            __syncthreads();
            for (int k = 128; k > 0; k >>= 1) {
                if (t < k) rd[t] += rd[t + k];
                __syncthreads();
            }
            const float s = 1e-25f / rd[0];
            float vj0 = v[j0 - BASE + c4],     vj1 = v[j0 - BASE + c4 + 1];
            float vj2 = v[j0 - BASE + c4 + 2], vj3 = v[j0 - BASE + c4 + 3];
            #pragma unroll
            for (int p = 0; p < 4; p++) {
                int r = rb + 16 * p, i = i0 + r;
                float vi = s * v[i - BASE];
                float4 o = make_float4(vi * vj0, vi * vj1, vi * vj2, vi * vj3);
                if (isdiag) {
                    int dj = i - (j0 + c4);
                    if ((unsigned)dj < 4u) (&o.x)[dj] += 1e-20f;
                }
                *(float4*)(out + (size_t)i * TOT + j0 + c4) = o;
            }
        } else {
            // ---- middle-right zeros
            const float4 z = make_float4(0.f, 0.f, 0.f, 0.f);
            #pragma unroll
            for (int p = 0; p < 4; p++) {
                int i = i0 + rb + 16 * p;
                *(float4*)(out + (size_t)i * TOT + j0 + c4) = z;
            }
        }
    } else {
        // ---- bottom rows (>= CE): zeros; quantum diagonal on bx==by
        #pragma unroll
        for (int p = 0; p < 4; p++) {
            int i = i0 + rb + 16 * p;
            float4 o = make_float4(0.f, 0.f, 0.f, 0.f);
            if (isdiag) {
                int dj = i - (j0 + c4);
                if ((unsigned)dj < 4u) (&o.x)[dj] = diag_val(i, srp, sip);
            }
            *(float4*)(out + (size_t)i * TOT + j0 + c4) = o;
        }
    }
}

// ===================== generic fallback (any imode/omode) ===================
template<int IMODE>
__device__ __forceinline__ float2 cload(const float* __restrict__ re,
                                        const float* __restrict__ im, size_t i) {
    if (IMODE == 1) return ((const float2*)re)[i];
    float2 r; r.x = re[i]; r.y = (IMODE == 2) ? im[i] : 0.f; return r;
}
template<int OMODE>
__device__ __forceinline__ void cstore(float* __restrict__ out, size_t idx,
                                       float re, float im) {
    if (OMODE == 0)      out[idx] = re;
    else if (OMODE == 1) ((float2*)out)[idx] = make_float2(re, im);
    else               { out[idx] = re; out[idx + NN] = im; }
}

template<int IMODE, int OMODE>
__global__ __launch_bounds__(256)
void fused_kernel(const float* __restrict__ ccre, const float* __restrict__ ccim,
                  const float* __restrict__ crre, const float* __restrict__ crim,
                  const float* __restrict__ vre,  const float* __restrict__ vim,
                  const float* __restrict__ srp,  const float* __restrict__ sip,
                  const float* __restrict__ gsre, const float* __restrict__ gsim,
                  const float* __restrict__ grre, const float* __restrict__ grim,
                  float* __restrict__ out) {
    constexpr bool NEED_IM = (OMODE != 0) && (IMODE != 0);
    __shared__ float tre[32][33];
    __shared__ float tim[NEED_IM ? 32 : 1][NEED_IM ? 33 : 1];
    __shared__ float rd[256];
    const int tx = threadIdx.x, ty = threadIdx.y;
    const int i0 = blockIdx.y * 32, j0 = blockIdx.x * 32;

    if (i0 < BASE && j0 < BASE) {
        for (int r = ty; r < 32; r += 8) {
            float2 a = cload<IMODE>(ccre, ccim, (size_t)(j0 + r) * BASE + (i0 + tx));
            tre[r][tx] = a.x;
            if (NEED_IM) tim[r][tx] = a.y;
        }
        __syncthreads();
        const float sc = 0.5f * 1e-27f;
        for (int iy = ty; iy < 32; iy += 8) {
            const int i = i0 + iy, j = j0 + tx;
            float2 a = cload<IMODE>(ccre, ccim, (size_t)i * BASE + j);
            float re = sc * (a.x + tre[tx][iy]);
            float im = 0.f;
            if (OMODE != 0) im = sc * (a.y - (NEED_IM ? tim[tx][iy] : 0.f));
            if (i == j) re += diag_val(i, srp, sip);
            if (i0 == 0 && j0 == 0 && i < 16 && j < 16) {
                float br = 0.f, bi = 0.f, cr = 0.f, ci = 0.f;
                #pragma unroll
                for (int g = 0; g < 4; g++) {
                    float s2 = (float)(g + 5) * 1e-26f;
                    float2 a1 = cload<IMODE>(grre, grim, g * 256 + i * 16 + j);
                    float2 b1 = cload<IMODE>(grre, grim, g * 256 + j * 16 + i);
                    br += s2 * a1.x;  bi += s2 * a1.y;
                    cr += s2 * b1.x;  ci += s2 * b1.y;
                    if (i < 8 && j < 8) {
                        float s1 = (float)(g + 1) * 1e-26f;
                        float2 a2 = cload<IMODE>(gsre, gsim, g * 64 + i * 8 + j);
                        float2 b2 = cload<IMODE>(gsre, gsim, g * 64 + j * 8 + i);
                        br += s1 * a2.x;  bi += s1 * a2.y;
                        cr += s1 * b2.x;  ci += s1 * b2.y;
                    }
                }
                re += 0.5f * (br + cr);
                if (OMODE != 0) im += 0.5f * (bi - ci);
            }
            cstore<OMODE>(out, (size_t)i * TOT + j, re, im);
        }
    } else if (i0 < BASE && j0 < CE) {
        const int jc0 = j0 - BASE;
        for (int r = ty; r < 32; r += 8) {
            float2 a = cload<IMODE>(crre, crim, (size_t)(jc0 + r) * BASE + (i0 + tx));
            tre[r][tx] = a.x;
            if (NEED_IM) tim[r][tx] = a.y;
        }
        __syncthreads();
        for (int iy = ty; iy < 32; iy += 8)
            cstore<OMODE>(out, (size_t)(i0 + iy) * TOT + (j0 + tx),
                          tre[tx][iy], NEED_IM ? tim[tx][iy] : 0.f);
    } else if (i0 >= BASE && i0 < CE && j0 < BASE) {
        for (int iy = ty; iy < 32; iy += 8) {
            const int i = i0 + iy, j = j0 + tx;
            float2 a = cload<IMODE>(crre, crim, (size_t)(i - BASE) * BASE + j);
            cstore<OMODE>(out, (size_t)i * TOT + j, a.x, (OMODE != 0) ? -a.y : 0.f);
        }
    } else if (i0 >= BASE && i0 < CE && j0 >= BASE && j0 < CE) {
        const int t = ty * 32 + tx;
        {
            float2 a = cload<IMODE>(vre, vim, t);
            float2 b = cload<IMODE>(vre, vim, t + 256);
            rd[t] = a.x * a.x + a.y * a.y + b.x * b.x + b.y * b.y;
        }
        __syncthreads();
        for (int k = 128; k > 0; k >>= 1) {
            if (t < k) rd[t] += rd[t + k];
            __syncthreads();
        }
        const float s = 1e-25f / rd[0];
        const float2 vj = cload<IMODE>(vre, vim, j0 - BASE + tx);
        for (int iy = ty; iy < 32; iy += 8) {
            const int i = i0 + iy, j = j0 + tx;
            const float2 vi = cload<IMODE>(vre, vim, i - BASE);
            float re = s * (vi.x * vj.x + vi.y * vj.y);
            float im = (OMODE != 0) ? s * (vi.y * vj.x - vi.x * vj.y) : 0.f;
            if (i == j) re += 1e-20f;
            cstore<OMODE>(out, (size_t)i * TOT + j, re, im);
        }
    } else {
        for (int iy = ty; iy < 32; iy += 8) {
            const int i = i0 + iy, j = j0 + tx;
            float re = (i >= CE && i == j) ? diag_val(i, srp, sip) : 0.f;
            cstore<OMODE>(out, (size_t)i * TOT + j, re, 0.f);
        }
    }
}

// ===================== host ================================================
struct Ptrs {
    const float *sr, *si, *vre, *vim, *crre, *crim, *ccre, *ccim,
                *gsre, *gsim, *grre, *grim;
};

template<int IMODE, int OMODE>
static void launch_fallback(const Ptrs& p, float* out) {
    fused_kernel<IMODE, OMODE><<<dim3(TOT / 32, TOT / 32), dim3(32, 8)>>>(
        p.ccre, p.ccim, p.crre, p.crim, p.vre, p.vim,
        p.sr, p.si, p.gsre, p.gsim, p.grre, p.grim, out);
}

static int find_nth(const int* sizes, int n, long long S, int nth) {
    int seen = 0;
    for (int k = 0; k < n; k++)
        if ((long long)sizes[k] == S) { if (seen == nth) return k; seen++; }
    return -1;
}

extern "C" void kernel_launch(void* const* d_in, const int* in_sizes, int n_in,
                              void* d_out, int out_size) {
    const long long B2 = (long long)BASE * BASE;
    int n4M = 0; bool has8M = false;
    for (int k = 0; k < n_in; k++) {
        if ((long long)in_sizes[k] == B2)     n4M++;
        if ((long long)in_sizes[k] == 2 * B2) has8M = true;
    }
    const int imode = has8M ? 1 : (n4M >= 2 ? 2 : 0);
    const bool cplx_out = ((long long)out_size >= 2 * (long long)NN);
    const int omode = !cplx_out ? 0 : (imode == 1 ? 1 : 2);

    long long Sv, Scr, Scc, Sgs, Sgr;
    if (imode == 1) { Sv = 1024; Scr = 2097152; Scc = 8388608; Sgs = 512; Sgr = 2048; }
    else            { Sv = 512;  Scr = 1048576; Scc = 4194304; Sgs = 256; Sgr = 1024; }

    auto get = [&](long long S, int nth) -> const float* {
        int k = find_nth(in_sizes, n_in, S, nth);
        return (k >= 0) ? (const float*)d_in[k] : nullptr;
    };

    Ptrs p;
    p.sr   = get(1, 0);
    p.si   = get(1, 1);
    p.vre  = get(Sv, 0);   p.vim  = (imode == 2) ? get(Sv, 1)  : nullptr;
    p.crre = get(Scr, 0);  p.crim = (imode == 2) ? get(Scr, 1) : nullptr;
    p.ccre = get(Scc, 0);  p.ccim = (imode == 2) ? get(Scc, 1) : nullptr;
    p.gsre = get(Sgs, 0);  p.gsim = (imode == 2) ? get(Sgs, 1) : nullptr;
    p.grre = get(Sgr, 0);  p.grim = (imode == 2) ? get(Sgr, 1) : nullptr;

    auto fb = [&](const float*& q, int idx) {
        if (!q && idx < n_in) q = (const float*)d_in[idx];
    };
    fb(p.vre, 2); fb(p.crre, 4); fb(p.ccre, 5); fb(p.gsre, 6); fb(p.grre, 7);
    if (imode == 2) { fb(p.vim, 3); fb(p.crim, 7); fb(p.ccim, 9); fb(p.gsim, 11); fb(p.grim, 13); }

    float* out = (float*)d_out;
    if (imode == 0 && omode == 0) {
        fill_fast<<<dim3(TOT / 64, TOT / 64), 256>>>(p.ccre, p.crre, p.vre,
                                                     p.gsre, p.grre, p.sr, p.si, out);
    } else if (imode == 1) {
        if (omode == 1) launch_fallback<1, 1>(p, out); else launch_fallback<1, 0>(p, out);
    } else if (imode == 2) {
        if (omode == 2) launch_fallback<2, 2>(p, out); else launch_fallback<2, 0>(p, out);
    } else {
        launch_fallback<0, 2>(p, out);
    }
}

// round 17
// speedup vs baseline: 5.9689x; 5.9689x over previous
#include <cuda_runtime.h>
#include <cstdio>

#define BASE 2048
#define CDIM 512
#define QDIM 256
#define TOT  2816
#define CE   2560
#define NN   ((size_t)TOT * (size_t)TOT)

__device__ __forceinline__ float sget(const float* p, float fb) { return p ? *p : fb; }

// diagonal entry of H at (i,i) — pure FP32 (no DP transcendentals in bulk kernels!)
__device__ __forceinline__ float diag_val_f(int i, const float* srp, const float* sip) {
    float sr = sget(srp, 2.0f);
    float si = sget(sip, 14.134725f);
    if (i < BASE) {
        float ln = logf((float)(i + 1));
        float lr = -sr * ln, li = -si * ln;
        bool small_s = (fabsf(sr) < 20.0f) && (fabsf(si) < 200.0f);
        // 1e-50 underflows float32 -> exactly 0.0f in the output dtype
        float zre = (small_s || lr > -50.0f) ? expf(lr) * cosf(li) : 0.f;
        return zre + 1e-20f;
    } else if (i < CE) {
        return 1e-20f;
    } else {
        float smag = sqrtf(sr * sr + si * si);
        float ent = (-smag * logf(smag + 1e-10f)) * (1.0f + 0.1f * sinf(si * 0.1f));
        return ent / (float)(i - CE + 1) + 1e-20f;
    }
}

__device__ __forceinline__ float gamma_re(int i, int j,
                                          const float* __restrict__ gs,
                                          const float* __restrict__ gr) {
    float br = 0.f, cr = 0.f;
    #pragma unroll
    for (int g = 0; g < 4; g++) {
        float s2 = (float)(g + 5) * 1e-26f;   // (g+5)*theta_c/10
        br += s2 * gr[g * 256 + i * 16 + j];
        cr += s2 * gr[g * 256 + j * 16 + i];
        if (i < 8 && j < 8) {
            float s1 = (float)(g + 1) * 1e-26f;
            br += s1 * gs[g * 64 + i * 8 + j];
            cr += s1 * gs[g * 64 + j * 8 + i];
        }
    }
    return 0.5f * (br + cr);
}

// ============ single fast kernel: real in / real out, 64x64 float4 tiles ====
__global__ __launch_bounds__(256)
void fill_fast(const float* __restrict__ cc, const float* __restrict__ crm,
               const float* __restrict__ v,
               const float* __restrict__ gs, const float* __restrict__ gr,
               const float* __restrict__ srp, const float* __restrict__ sip,
               float* __restrict__ out) {
    __shared__ float sm[64][65];
    const int bx = blockIdx.x, by = blockIdx.y;
    const int t  = threadIdx.x;
    const int rb = t >> 4;               // 0..15
    const int c4 = (t & 15) << 2;        // 0,4,...,60
    const int i0 = by * 64, j0 = bx * 64;
    const bool isdiag = (bx == by);

    if (by < 32) {
        if (bx < 32) {
            // ---- base x base: sc*(cc[i,j] + cc[j,i]) (+diag, +gamma corner)
            #pragma unroll
            for (int p = 0; p < 4; p++) {
                int r = rb + 16 * p;
                float4 m = *(const float4*)(cc + (size_t)(j0 + r) * BASE + i0 + c4);
                sm[r][c4] = m.x; sm[r][c4 + 1] = m.y; sm[r][c4 + 2] = m.z; sm[r][c4 + 3] = m.w;
            }
            __syncthreads();
            const float sc = 0.5e-27f;
            const bool corner = (i0 == 0 && j0 == 0);
            #pragma unroll
            for (int p = 0; p < 4; p++) {
                int r = rb + 16 * p, i = i0 + r;
                float4 a = *(const float4*)(cc + (size_t)i * BASE + j0 + c4);
                float4 o;
                o.x = sc * (a.x + sm[c4 + 0][r]);
                o.y = sc * (a.y + sm[c4 + 1][r]);
                o.z = sc * (a.z + sm[c4 + 2][r]);
                o.w = sc * (a.w + sm[c4 + 3][r]);
                if (corner && r < 16 && c4 < 16) {
                    #pragma unroll
                    for (int k = 0; k < 4; k++)
                        (&o.x)[k] += gamma_re(r, c4 + k, gs, gr);
                }
                if (isdiag) {
                    int dj = i - (j0 + c4);
                    if ((unsigned)dj < 4u) (&o.x)[dj] += diag_val_f(i, srp, sip);
                }
                *(float4*)(out + (size_t)i * TOT + j0 + c4) = o;
            }
        } else if (bx < 40) {
            // ---- right strip: out[i, BASE+jc] = crm[jc, i] (transpose)
            const int jc0 = (bx - 32) * 64;
            #pragma unroll
            for (int p = 0; p < 4; p++) {
                int r = rb + 16 * p;
                float4 m = *(const float4*)(crm + (size_t)(jc0 + r) * BASE + i0 + c4);
                sm[r][c4] = m.x; sm[r][c4 + 1] = m.y; sm[r][c4 + 2] = m.z; sm[r][c4 + 3] = m.w;
            }
            __syncthreads();
            #pragma unroll
            for (int p = 0; p < 4; p++) {
                int r = rb + 16 * p, i = i0 + r;
                float4 o = make_float4(sm[c4 + 0][r], sm[c4 + 1][r],
                                       sm[c4 + 2][r], sm[c4 + 3][r]);
                *(float4*)(out + (size_t)i * TOT + j0 + c4) = o;
            }
        } else {
            // ---- top-right zeros
            const float4 z = make_float4(0.f, 0.f, 0.f, 0.f);
            #pragma unroll
            for (int p = 0; p < 4; p++) {
                int i = i0 + rb + 16 * p;
                *(float4*)(out + (size_t)i * TOT + j0 + c4) = z;
            }
        }
    } else if (by < 40) {
        if (bx < 32) {
            // ---- bottom-left: Re(conj(crm[ic, j])) = crm[ic, j]  (direct copy)
            const int ic0 = (by - 32) * 64;
            #pragma unroll
            for (int p = 0; p < 4; p++) {
                int r = rb + 16 * p;
                float4 a = *(const float4*)(crm + (size_t)(ic0 + r) * BASE + j0 + c4);
                *(float4*)(out + (size_t)(i0 + r) * TOT + j0 + c4) = a;
            }
        } else if (bx < 40) {
            // ---- consciousness outer product: s * v_i * v_j  (+1e-20 diag)
            __shared__ float rd[256];
            {
                float a = v[t], b = v[t + 256];
                rd[t] = a * a + b * b;
            }
            __syncthreads();
            for (int k = 128; k > 0; k >>= 1) {
                if (t < k) rd[t] += rd[t + k];
                __syncthreads();
            }
            const float s = 1e-25f / rd[0];
            float vj0 = v[j0 - BASE + c4],     vj1 = v[j0 - BASE + c4 + 1];
            float vj2 = v[j0 - BASE + c4 + 2], vj3 = v[j0 - BASE + c4 + 3];
            #pragma unroll
            for (int p = 0; p < 4; p++) {
                int r = rb + 16 * p, i = i0 + r;
                float vi = s * v[i - BASE];
                float4 o = make_float4(vi * vj0, vi * vj1, vi * vj2, vi * vj3);
                if (isdiag) {
                    int dj = i - (j0 + c4);
                    if ((unsigned)dj < 4u) (&o.x)[dj] += 1e-20f;
                }
                *(float4*)(out + (size_t)i * TOT + j0 + c4) = o;
            }
        } else {
            // ---- middle-right zeros
            const float4 z = make_float4(0.f, 0.f, 0.f, 0.f);
            #pragma unroll
            for (int p = 0; p < 4; p++) {
                int i = i0 + rb + 16 * p;
                *(float4*)(out + (size_t)i * TOT + j0 + c4) = z;
            }
        }
    } else {
        // ---- bottom rows (>= CE): zeros; quantum diagonal on bx==by
        #pragma unroll
        for (int p = 0; p < 4; p++) {
            int i = i0 + rb + 16 * p;
            float4 o = make_float4(0.f, 0.f, 0.f, 0.f);
            if (isdiag) {
                int dj = i - (j0 + c4);
                if ((unsigned)dj < 4u) (&o.x)[dj] = diag_val_f(i, srp, sip);
            }
            *(float4*)(out + (size_t)i * TOT + j0 + c4) = o;
        }
    }
}

// ===================== generic fallback (any imode/omode) ===================
template<int IMODE>
__device__ __forceinline__ float2 cload(const float* __restrict__ re,
                                        const float* __restrict__ im, size_t i) {
    if (IMODE == 1) return ((const float2*)re)[i];
    float2 r; r.x = re[i]; r.y = (IMODE == 2) ? im[i] : 0.f; return r;
}
template<int OMODE>
__device__ __forceinline__ void cstore(float* __restrict__ out, size_t idx,
                                       float re, float im) {
    if (OMODE == 0)      out[idx] = re;
    else if (OMODE == 1) ((float2*)out)[idx] = make_float2(re, im);
    else               { out[idx] = re; out[idx + NN] = im; }
}

template<int IMODE, int OMODE>
__global__ __launch_bounds__(256)
void fused_kernel(const float* __restrict__ ccre, const float* __restrict__ ccim,
                  const float* __restrict__ crre, const float* __restrict__ crim,
                  const float* __restrict__ vre,  const float* __restrict__ vim,
                  const float* __restrict__ srp,  const float* __restrict__ sip,
                  const float* __restrict__ gsre, const float* __restrict__ gsim,
                  const float* __restrict__ grre, const float* __restrict__ grim,
                  float* __restrict__ out) {
    constexpr bool NEED_IM = (OMODE != 0) && (IMODE != 0);
    __shared__ float tre[32][33];
    __shared__ float tim[NEED_IM ? 32 : 1][NEED_IM ? 33 : 1];
    __shared__ float rd[256];
    const int tx = threadIdx.x, ty = threadIdx.y;
    const int i0 = blockIdx.y * 32, j0 = blockIdx.x * 32;

    if (i0 < BASE && j0 < BASE) {
        for (int r = ty; r < 32; r += 8) {
            float2 a = cload<IMODE>(ccre, ccim, (size_t)(j0 + r) * BASE + (i0 + tx));
            tre[r][tx] = a.x;
            if (NEED_IM) tim[r][tx] = a.y;
        }
        __syncthreads();
        const float sc = 0.5f * 1e-27f;
        for (int iy = ty; iy < 32; iy += 8) {
            const int i = i0 + iy, j = j0 + tx;
            float2 a = cload<IMODE>(ccre, ccim, (size_t)i * BASE + j);
            float re = sc * (a.x + tre[tx][iy]);
            float im = 0.f;
            if (OMODE != 0) im = sc * (a.y - (NEED_IM ? tim[tx][iy] : 0.f));
            if (i == j) re += diag_val_f(i, srp, sip);
            if (i0 == 0 && j0 == 0 && i < 16 && j < 16) {
                float br = 0.f, bi = 0.f, cr = 0.f, ci = 0.f;
                #pragma unroll
                for (int g = 0; g < 4; g++) {
                    float s2 = (float)(g + 5) * 1e-26f;
                    float2 a1 = cload<IMODE>(grre, grim, g * 256 + i * 16 + j);
                    float2 b1 = cload<IMODE>(grre, grim, g * 256 + j * 16 + i);
                    br += s2 * a1.x;  bi += s2 * a1.y;
                    cr += s2 * b1.x;  ci += s2 * b1.y;
                    if (i < 8 && j < 8) {
                        float s1 = (float)(g + 1) * 1e-26f;
                        float2 a2 = cload<IMODE>(gsre, gsim, g * 64 + i * 8 + j);
                        float2 b2 = cload<IMODE>(gsre, gsim, g * 64 + j * 8 + i);
                        br += s1 * a2.x;  bi += s1 * a2.y;
                        cr += s1 * b2.x;  ci += s1 * b2.y;
                    }
                }
                re += 0.5f * (br + cr);
                if (OMODE != 0) im += 0.5f * (bi - ci);
            }
            cstore<OMODE>(out, (size_t)i * TOT + j, re, im);
        }
    } else if (i0 < BASE && j0 < CE) {
        const int jc0 = j0 - BASE;
        for (int r = ty; r < 32; r += 8) {
            float2 a = cload<IMODE>(crre, crim, (size_t)(jc0 + r) * BASE + (i0 + tx));
            tre[r][tx] = a.x;
            if (NEED_IM) tim[r][tx] = a.y;
        }
        __syncthreads();
        for (int iy = ty; iy < 32; iy += 8)
            cstore<OMODE>(out, (size_t)(i0 + iy) * TOT + (j0 + tx),
                          tre[tx][iy], NEED_IM ? tim[tx][iy] : 0.f);
    } else if (i0 >= BASE && i0 < CE && j0 < BASE) {
        for (int iy = ty; iy < 32; iy += 8) {
            const int i = i0 + iy, j = j0 + tx;
            float2 a = cload<IMODE>(crre, crim, (size_t)(i - BASE) * BASE + j);
            cstore<OMODE>(out, (size_t)i * TOT + j, a.x, (OMODE != 0) ? -a.y : 0.f);
        }
    } else if (i0 >= BASE && i0 < CE && j0 >= BASE && j0 < CE) {
        const int t = ty * 32 + tx;
        {
            float2 a = cload<IMODE>(vre, vim, t);
            float2 b = cload<IMODE>(vre, vim, t + 256);
            rd[t] = a.x * a.x + a.y * a.y + b.x * b.x + b.y * b.y;
        }
        __syncthreads();
        for (int k = 128; k > 0; k >>= 1) {
            if (t < k) rd[t] += rd[t + k];
            __syncthreads();
        }
        const float s = 1e-25f / rd[0];
        const float2 vj = cload<IMODE>(vre, vim, j0 - BASE + tx);
        for (int iy = ty; iy < 32; iy += 8) {
            const int i = i0 + iy, j = j0 + tx;
            const float2 vi = cload<IMODE>(vre, vim, i - BASE);
            float re = s * (vi.x * vj.x + vi.y * vj.y);
            float im = (OMODE != 0) ? s * (vi.y * vj.x - vi.x * vj.y) : 0.f;
            if (i == j) re += 1e-20f;
            cstore<OMODE>(out, (size_t)i * TOT + j, re, im);
        }
    } else {
        for (int iy = ty; iy < 32; iy += 8) {
            const int i = i0 + iy, j = j0 + tx;
            float re = (i >= CE && i == j) ? diag_val_f(i, srp, sip) : 0.f;
            cstore<OMODE>(out, (size_t)i * TOT + j, re, 0.f);
        }
    }
}

// ===================== host ================================================
struct Ptrs {
    const float *sr, *si, *vre, *vim, *crre, *crim, *ccre, *ccim,
                *gsre, *gsim, *grre, *grim;
};

template<int IMODE, int OMODE>
static void launch_fallback(const Ptrs& p, float* out) {
    fused_kernel<IMODE, OMODE><<<dim3(TOT / 32, TOT / 32), dim3(32, 8)>>>(
        p.ccre, p.ccim, p.crre, p.crim, p.vre, p.vim,
        p.sr, p.si, p.gsre, p.gsim, p.grre, p.grim, out);
}

static int find_nth(const int* sizes, int n, long long S, int nth) {
    int seen = 0;
    for (int k = 0; k < n; k++)
        if ((long long)sizes[k] == S) { if (seen == nth) return k; seen++; }
    return -1;
}

extern "C" void kernel_launch(void* const* d_in, const int* in_sizes, int n_in,
                              void* d_out, int out_size) {
    const long long B2 = (long long)BASE * BASE;
    int n4M = 0; bool has8M = false;
    for (int k = 0; k < n_in; k++) {
        if ((long long)in_sizes[k] == B2)     n4M++;
        if ((long long)in_sizes[k] == 2 * B2) has8M = true;
    }
    const int imode = has8M ? 1 : (n4M >= 2 ? 2 : 0);
    const bool cplx_out = ((long long)out_size >= 2 * (long long)NN);
    const int omode = !cplx_out ? 0 : (imode == 1 ? 1 : 2);

    long long Sv, Scr, Scc, Sgs, Sgr;
    if (imode == 1) { Sv = 1024; Scr = 2097152; Scc = 8388608; Sgs = 512; Sgr = 2048; }
    else            { Sv = 512;  Scr = 1048576; Scc = 4194304; Sgs = 256; Sgr = 1024; }

    auto get = [&](long long S, int nth) -> const float* {
        int k = find_nth(in_sizes, n_in, S, nth);
        return (k >= 0) ? (const float*)d_in[k] : nullptr;
    };

    Ptrs p;
    p.sr   = get(1, 0);
    p.si   = get(1, 1);
    p.vre  = get(Sv, 0);   p.vim  = (imode == 2) ? get(Sv, 1)  : nullptr;
    p.crre = get(Scr, 0);  p.crim = (imode == 2) ? get(Scr, 1) : nullptr;
    p.ccre = get(Scc, 0);  p.ccim = (imode == 2) ? get(Scc, 1) : nullptr;
    p.gsre = get(Sgs, 0);  p.gsim = (imode == 2) ? get(Sgs, 1) : nullptr;
    p.grre = get(Sgr, 0);  p.grim = (imode == 2) ? get(Sgr, 1) : nullptr;

    auto fb = [&](const float*& q, int idx) {
        if (!q && idx < n_in) q = (const float*)d_in[idx];
    };
    fb(p.vre, 2); fb(p.crre, 4); fb(p.ccre, 5); fb(p.gsre, 6); fb(p.grre, 7);
    if (imode == 2) { fb(p.vim, 3); fb(p.crim, 7); fb(p.ccim, 9); fb(p.gsim, 11); fb(p.grim, 13); }

    float* out = (float*)d_out;
    if (imode == 0 && omode == 0) {
        fill_fast<<<dim3(TOT / 64, TOT / 64), 256>>>(p.ccre, p.crre, p.vre,
                                                     p.gsre, p.grre, p.sr, p.si, out);
    } else if (imode == 1) {
        if (omode == 1) launch_fallback<1, 1>(p, out); else launch_fallback<1, 0>(p, out);
    } else if (imode == 2) {
        if (omode == 2) launch_fallback<2, 2>(p, out); else launch_fallback<2, 0>(p, out);
    } else {
        launch_fallback<0, 2>(p, out);
    }
}